// round 1
// baseline (speedup 1.0000x reference)
#include <cuda_runtime.h>

// IF spiking neuron forward, T=4, B=8, FEAT=1024x3072, fp32.
// x layout: [(t*B + b), 1024, 3072]  -> flat float4 index = (t*B+b)*F4 + fo
//                                    = t*N4 + (b*F4 + fo) with N4 = B*F4.
// One thread owns one float4 feature position across all 4 timesteps.

#define T_STEPS 4
#define BATCH   8
#define FEAT_ELEMS (1024 * 3072)          // 3145728
#define F4      (FEAT_ELEMS / 4)          // 786432 float4 per feature map
#define N4      (BATCH * F4)              // 6291456 float4 per timestep slab

__global__ __launch_bounds__(256) void if_fwd_kernel(
    const float4* __restrict__ x,
    const float4* __restrict__ thresh2,
    const float4* __restrict__ dtmem,
    float4* __restrict__ out)
{
    const int fo  = blockIdx.x * blockDim.x + threadIdx.x;  // float4 idx in feature map
    const int b   = blockIdx.y;
    const int gid = b * F4 + fo;                            // float4 idx within one timestep slab

    // Per-position parameters (amortized over 4 timesteps)
    const float4 th = thresh2[fo];
    const float4 dt = dtmem[fo];

    // Front-batch all 4 timestep loads (independent LDG.128, MLP=4)
    float4 x0 = x[0 * N4 + gid];
    float4 x1 = x[1 * N4 + gid];
    float4 x2 = x[2 * N4 + gid];
    float4 x3 = x[3 * N4 + gid];

    // mem0 = dtmem * thre
    float4 m;
    m.x = dt.x * th.x;
    m.y = dt.y * th.y;
    m.z = dt.z * th.z;
    m.w = dt.w * th.w;

    float4 o0, o1, o2, o3;

    // step: mem += x; spike = (mem >= thre) ? thre : 0; mem -= spike
#define IF_STEP(XV, OV)                                          \
    {                                                            \
        m.x += (XV).x;                                           \
        m.y += (XV).y;                                           \
        m.z += (XV).z;                                           \
        m.w += (XV).w;                                           \
        float sx = (m.x >= th.x) ? th.x : 0.0f;                  \
        float sy = (m.y >= th.y) ? th.y : 0.0f;                  \
        float sz = (m.z >= th.z) ? th.z : 0.0f;                  \
        float sw = (m.w >= th.w) ? th.w : 0.0f;                  \
        m.x -= sx; m.y -= sy; m.z -= sz; m.w -= sw;              \
        (OV).x = sx; (OV).y = sy; (OV).z = sz; (OV).w = sw;      \
    }

    IF_STEP(x0, o0)
    IF_STEP(x1, o1)
    IF_STEP(x2, o2)
    IF_STEP(x3, o3)
#undef IF_STEP

    out[0 * N4 + gid] = o0;
    out[1 * N4 + gid] = o1;
    out[2 * N4 + gid] = o2;
    out[3 * N4 + gid] = o3;
}

extern "C" void kernel_launch(void* const* d_in, const int* in_sizes, int n_in,
                              void* d_out, int out_size)
{
    // inputs (metadata order): x [T*B,1024,3072] f32, thresh2 [1024,3072] f32,
    //                          dtmem [1024,3072] f32
    const float4* x  = (const float4*)d_in[0];
    const float4* th = (const float4*)d_in[1];
    const float4* dm = (const float4*)d_in[2];
    float4* out = (float4*)d_out;

    dim3 block(256);
    dim3 grid(F4 / 256, BATCH);   // 3072 x 8 = 24576 blocks
    if_fwd_kernel<<<grid, block>>>(x, th, dm, out);
}

// round 2
// speedup vs baseline: 1.1580x; 1.1580x over previous
#include <cuda_runtime.h>

// IF spiking neuron forward, T=4, B=8, FEAT=1024x3072, fp32.
// x layout: [(t*B + b), 1024, 3072]  -> flat float4 index = t*N4 + b*F4 + fo.
// One thread owns one float4 feature position across ALL batches and timesteps,
// so thresh2/dtmem are read exactly once per position (param traffic 25 MB,
// not 8x). x/out use streaming (evict-first) cache hints: each byte is touched
// once, keep it out of the way of the params in L2.

#define T_STEPS 4
#define BATCH   8
#define FEAT_ELEMS (1024 * 3072)          // 3145728
#define F4      (FEAT_ELEMS / 4)          // 786432 float4 per feature map
#define N4      (BATCH * F4)              // 6291456 float4 per timestep slab

__global__ __launch_bounds__(256) void if_fwd_kernel(
    const float4* __restrict__ x,
    const float4* __restrict__ thresh2,
    const float4* __restrict__ dtmem,
    float4* __restrict__ out)
{
    const int fo = blockIdx.x * blockDim.x + threadIdx.x;   // float4 idx in feature map

    // Per-position parameters, read once for all 32 (b,t) elements
    const float4 th = thresh2[fo];
    const float4 dt = dtmem[fo];

    // initial membrane = dtmem * thre (same for every batch)
    float4 m0;
    m0.x = dt.x * th.x;
    m0.y = dt.y * th.y;
    m0.z = dt.z * th.z;
    m0.w = dt.w * th.w;

#pragma unroll 2
    for (int b = 0; b < BATCH; b++) {
        const long gid = (long)b * F4 + fo;

        // Front-batch the 4 timestep loads (independent LDG.128, evict-first)
        float4 x0 = __ldcs(&x[0 * (long)N4 + gid]);
        float4 x1 = __ldcs(&x[1 * (long)N4 + gid]);
        float4 x2 = __ldcs(&x[2 * (long)N4 + gid]);
        float4 x3 = __ldcs(&x[3 * (long)N4 + gid]);

        float4 m = m0;
        float4 o0, o1, o2, o3;

        // step: mem += x; spike = (mem >= thre) ? thre : 0; mem -= spike
#define IF_STEP(XV, OV)                                          \
        {                                                        \
            m.x += (XV).x;                                       \
            m.y += (XV).y;                                       \
            m.z += (XV).z;                                       \
            m.w += (XV).w;                                       \
            float sx = (m.x >= th.x) ? th.x : 0.0f;              \
            float sy = (m.y >= th.y) ? th.y : 0.0f;              \
            float sz = (m.z >= th.z) ? th.z : 0.0f;              \
            float sw = (m.w >= th.w) ? th.w : 0.0f;              \
            m.x -= sx; m.y -= sy; m.z -= sz; m.w -= sw;          \
            (OV).x = sx; (OV).y = sy; (OV).z = sz; (OV).w = sw;  \
        }

        IF_STEP(x0, o0)
        IF_STEP(x1, o1)
        IF_STEP(x2, o2)
        IF_STEP(x3, o3)
#undef IF_STEP

        __stcs(&out[0 * (long)N4 + gid], o0);
        __stcs(&out[1 * (long)N4 + gid], o1);
        __stcs(&out[2 * (long)N4 + gid], o2);
        __stcs(&out[3 * (long)N4 + gid], o3);
    }
}

extern "C" void kernel_launch(void* const* d_in, const int* in_sizes, int n_in,
                              void* d_out, int out_size)
{
    // inputs (metadata order): x [T*B,1024,3072] f32, thresh2 [1024,3072] f32,
    //                          dtmem [1024,3072] f32
    const float4* x  = (const float4*)d_in[0];
    const float4* th = (const float4*)d_in[1];
    const float4* dm = (const float4*)d_in[2];
    float4* out = (float4*)d_out;

    dim3 block(256);
    dim3 grid(F4 / 256);   // 3072 blocks, each thread covers 8 batches x 4 timesteps
    if_fwd_kernel<<<grid, block>>>(x, th, dm, out);
}

// round 4
// speedup vs baseline: 1.1683x; 1.0089x over previous
#include <cuda_runtime.h>

// IF spiking neuron forward, T=4, B=8, FEAT=1024x3072, fp32.
// x flat float4 index = t*N4 + b*F4 + fo.
//
// Each thread: one float4 feature position, 2 batches, all 4 timesteps
// (8 float4 in / 8 out). Blocks are ordered so the 4 blocks sharing the same
// thresh2/dtmem cache lines (b_pair 0..3) launch adjacently -> param reads
// dedupe in L1/L2 (param DRAM traffic ~25 MB total), while the small work
// quantum (~14 waves of short blocks) avoids the wave-quantization tail that
// cost ~6% of HBM bandwidth in the previous version.

#define T_STEPS 4
#define BATCH   8
#define FEAT_ELEMS (1024 * 3072)          // 3145728
#define F4      (FEAT_ELEMS / 4)          // 786432 float4 per feature map
#define N4      (BATCH * F4)              // 6291456 float4 per timestep slab
#define B_PER_THREAD 2

__global__ __launch_bounds__(256) void if_fwd_kernel(
    const float4* __restrict__ x,
    const float4* __restrict__ thresh2,
    const float4* __restrict__ dtmem,
    float4* __restrict__ out)
{
    // blockIdx.x = fo_blk * 4 + b_pair : same-fo blocks adjacent in launch order
    const int b_pair = blockIdx.x & 3;                 // 0..3 -> batches {2p, 2p+1}
    const int fo_blk = blockIdx.x >> 2;
    const int fo = fo_blk * blockDim.x + threadIdx.x;  // float4 idx in feature map

    // Params: read via default (L2-cached) path; 4 co-resident blocks share lines.
    const float4 th = thresh2[fo];
    const float4 dt = dtmem[fo];

    // initial membrane = dtmem * thre (same for every batch)
    float4 m0;
    m0.x = dt.x * th.x;
    m0.y = dt.y * th.y;
    m0.z = dt.z * th.z;
    m0.w = dt.w * th.w;

    const int b0   = b_pair * B_PER_THREAD;
    const int gidA = b0 * F4 + fo;        // batch b0
    const int gidB = gidA + F4;           // batch b0+1

    // Front-batch all 8 timestep loads (independent LDG.128, evict-first)
    float4 a0 = __ldcs(&x[0 * N4 + gidA]);
    float4 a1 = __ldcs(&x[1 * N4 + gidA]);
    float4 a2 = __ldcs(&x[2 * N4 + gidA]);
    float4 a3 = __ldcs(&x[3 * N4 + gidA]);
    float4 c0 = __ldcs(&x[0 * N4 + gidB]);
    float4 c1 = __ldcs(&x[1 * N4 + gidB]);
    float4 c2 = __ldcs(&x[2 * N4 + gidB]);
    float4 c3 = __ldcs(&x[3 * N4 + gidB]);

    // step: mem += x; spike = (mem >= thre) ? thre : 0; mem -= spike
    // spike overwrites the x register (in-place), output stored from it.
#define IF_STEP(M, V)                                            \
    {                                                            \
        (M).x += (V).x;                                          \
        (M).y += (V).y;                                          \
        (M).z += (V).z;                                          \
        (M).w += (V).w;                                          \
        (V).x = ((M).x >= th.x) ? th.x : 0.0f;                   \
        (V).y = ((M).y >= th.y) ? th.y : 0.0f;                   \
        (V).z = ((M).z >= th.z) ? th.z : 0.0f;                   \
        (V).w = ((M).w >= th.w) ? th.w : 0.0f;                   \
        (M).x -= (V).x; (M).y -= (V).y;                          \
        (M).z -= (V).z; (M).w -= (V).w;                          \
    }

    float4 mA = m0;
    IF_STEP(mA, a0)
    IF_STEP(mA, a1)
    IF_STEP(mA, a2)
    IF_STEP(mA, a3)

    float4 mB = m0;
    IF_STEP(mB, c0)
    IF_STEP(mB, c1)
    IF_STEP(mB, c2)
    IF_STEP(mB, c3)
#undef IF_STEP

    __stcs(&out[0 * N4 + gidA], a0);
    __stcs(&out[1 * N4 + gidA], a1);
    __stcs(&out[2 * N4 + gidA], a2);
    __stcs(&out[3 * N4 + gidA], a3);
    __stcs(&out[0 * N4 + gidB], c0);
    __stcs(&out[1 * N4 + gidB], c1);
    __stcs(&out[2 * N4 + gidB], c2);
    __stcs(&out[3 * N4 + gidB], c3);
}

extern "C" void kernel_launch(void* const* d_in, const int* in_sizes, int n_in,
                              void* d_out, int out_size)
{
    // inputs (metadata order): x [T*B,1024,3072] f32, thresh2 [1024,3072] f32,
    //                          dtmem [1024,3072] f32
    const float4* x  = (const float4*)d_in[0];
    const float4* th = (const float4*)d_in[1];
    const float4* dm = (const float4*)d_in[2];
    float4* out = (float4*)d_out;

    dim3 block(256);
    dim3 grid((F4 / 256) * (BATCH / B_PER_THREAD));   // 3072 * 4 = 12288 blocks
    if_fwd_kernel<<<grid, block>>>(x, th, dm, out);
}